// round 11
// baseline (speedup 1.0000x reference)
#include <cuda_runtime.h>
#include <cuda_bf16.h>
#include <cstdint>

// Problem constants (fixed by the reference setup)
#define FDIM   256
#define NBINS  32
#define NBLK   148
#define TPB    1024
#define WPB    (TPB / 32)
#define WPAD   33                 // padded W row stride (bank decorrelation)
#define CHUNK_ROWS 32             // rows staged per chunk (one per warp)
#define ROW_BYTES  (FDIM * 4)     // 1024
#define CHUNK_BYTES (CHUNK_ROWS * ROW_BYTES)  // 32 KB

// smem layout (bytes)
#define OFF_W     0
#define OFF_IW    (FDIM * WPAD * 4)                 // 33792
#define OFF_STAGE (OFF_IW + 32 * 1024 * 4)          // 164864 (1KB aligned)
#define OFF_RED   (OFF_STAGE + 2 * CHUNK_BYTES)     // 230400
#define SMEM_TOTAL (OFF_RED + WPB * 4 * 8)          // 231424 <= 232448 opt-in max

// Per-block fairness partials: [block][ s0, s0sq, s5, s5sq ]
__device__ double       g_fair_part[NBLK * 4];
__device__ unsigned int g_done;   // zero at load; last block resets -> graph-replay safe

__device__ __forceinline__ uint32_t sw128(uint32_t o) {   // XOR bits[9:7] into [6:4]
    return o ^ ((o >> 3) & 0x70);
}

__device__ __forceinline__ void stage_chunk(const char* __restrict__ xb,
                                            size_t chunk_byte_base, size_t x_bytes,
                                            uint32_t dst_base, int tid)
{
    #pragma unroll
    for (int k = 0; k < 2; k++) {
        const uint32_t off = (uint32_t)(tid + k * TPB) * 16u;   // 0..32752
        const size_t src = chunk_byte_base + off;
        if (src < x_bytes) {
            const uint32_t dst = dst_base + sw128(off);
            asm volatile("cp.async.cg.shared.global [%0], [%1], 16;\n"
                         :: "r"(dst), "l"(xb + src) : "memory");
        }
    }
}

// x ~ uniform[0,1): (int)(v*32) == floor(v*32) == reference bin index (exact).
// Do NOT fuse +base into an FFMA (rounding could cross an integer bin).

template<bool FAST>
__device__ __forceinline__ float row_val(
    float4 a, float4 b,
    const float* __restrict__ sW_lane,    // sW + lane*8*WPAD
    const float* __restrict__ sIW_lane,   // sIW + lane*4096 floats = pair 4*lane base
    const float* __restrict__ sIW,
    int lane, int pi, int pj, bool havep,
    float& s0, float& s0q, float& s5, float& s5q)
{
    float v[8] = {a.x, a.y, a.z, a.w, b.x, b.y, b.z, b.w};
    int id[8];
    #pragma unroll
    for (int j = 0; j < 8; j++) id[j] = (int)(v[j] * 32.0f);

    float g[8];
    #pragma unroll
    for (int j = 0; j < 8; j++) g[j] = sW_lane[j * WPAD + id[j]];

    float m = ((g[0] + g[1]) + (g[2] + g[3])) + ((g[4] + g[5]) + (g[6] + g[7]));

    // fairness: features 0,5 live on lane 0; accumulate unpredicated on all
    // lanes, only lane 0's accumulators are consumed.
    s0 += g[0];  s0q = fmaf(g[0], g[0], s0q);
    s5 += g[5];  s5q = fmaf(g[5], g[5], s5q);

    float inter = 0.0f;
    if (FAST) {
        if (lane < 8) {   // pairs 4l..4l+3 entirely local to lane l
            #pragma unroll
            for (int q = 0; q < 4; q++)
                inter += sIW_lane[q * 1024 + id[2 * q] * 32 + id[2 * q + 1]];
        }
    } else {
        unsigned int lo = ((unsigned)id[0]) | ((unsigned)id[1] << 8) |
                          ((unsigned)id[2] << 16) | ((unsigned)id[3] << 24);
        unsigned int hi = ((unsigned)id[4]) | ((unsigned)id[5] << 8) |
                          ((unsigned)id[6] << 16) | ((unsigned)id[7] << 24);
        unsigned int li  = __shfl_sync(0xffffffffu, lo, (pi >> 3) & 31);
        unsigned int hii = __shfl_sync(0xffffffffu, hi, (pi >> 3) & 31);
        unsigned int lj  = __shfl_sync(0xffffffffu, lo, (pj >> 3) & 31);
        unsigned int hjj = __shfl_sync(0xffffffffu, hi, (pj >> 3) & 31);
        if (havep) {
            const unsigned wi = ((pi & 4) ? hii : li) >> (8 * (pi & 3));
            const unsigned wj = ((pj & 4) ? hjj : lj) >> (8 * (pj & 3));
            inter = sIW[lane * (NBINS * NBINS) + (int)(wi & 0xff) * NBINS + (int)(wj & 0xff)];
        }
    }
    return m + inter;
}

template<bool FAST>
__device__ __forceinline__ void run_pipeline(
    const char* __restrict__ xb, size_t x_bytes, int B, int nchunk,
    char* __restrict__ stg, uint32_t stage_u32,
    const float* __restrict__ sW_lane, const float* __restrict__ sIW_lane,
    const float* __restrict__ sIW,
    int tid, int lane, int warp, int pi, int pj, bool havep,
    float c, float* __restrict__ out,
    float& s0, float& s0q, float& s5, float& s5q)
{
    int ck = blockIdx.x;
    if (ck < nchunk)
        stage_chunk(xb, (size_t)ck * CHUNK_BYTES, x_bytes, stage_u32, tid);
    asm volatile("cp.async.commit_group;\n" ::: "memory");

    int pb = 0;
    while (ck < nchunk) {
        const int cn = ck + gridDim.x;
        if (cn < nchunk)
            stage_chunk(xb, (size_t)cn * CHUNK_BYTES, x_bytes,
                        stage_u32 + (uint32_t)((pb ^ 1) * CHUNK_BYTES), tid);
        asm volatile("cp.async.commit_group;\n" ::: "memory");
        asm volatile("cp.async.wait_group 1;\n" ::: "memory");
        __syncthreads();   // chunk ck staged & visible to all warps

        const int row = ck * CHUNK_ROWS + warp;
        if (row < B) {
            const char* buf = stg + pb * CHUNK_BYTES;
            const uint32_t o0 = (uint32_t)(warp * ROW_BYTES + lane * 32);
            const float4 a = *(const float4*)(buf + sw128(o0));
            const float4 b = *(const float4*)(buf + sw128(o0 + 16));

            float tot = row_val<FAST>(a, b, sW_lane, sIW_lane, sIW,
                                      lane, pi, pj, havep, s0, s0q, s5, s5q);
            #pragma unroll
            for (int o = 16; o > 0; o >>= 1)
                tot += __shfl_xor_sync(0xffffffffu, tot, o);
            if (lane == 0) out[row] = c + tot;
        }
        __syncthreads();   // reads done before buf is re-staged
        pb ^= 1;
        ck = cn;
    }
}

__global__ __launch_bounds__(TPB, 1)
void fair_ebm_main(const float*  __restrict__ x,
                   const float*  __restrict__ W,          // [256, 32]
                   const float*  __restrict__ IW,         // [P, 32, 32]
                   const float*  __restrict__ intercept,  // [1]
                   const int*    __restrict__ pair_i,     // [P]
                   const int*    __restrict__ pair_j,     // [P]
                   float*        __restrict__ out,        // [B+1]
                   int B, int P)
{
    extern __shared__ char smem[];
    float*  sW   = (float*)(smem + OFF_W);
    float*  sIW  = (float*)(smem + OFF_IW);
    char*   stg  = smem + OFF_STAGE;
    double* sred = (double*)(smem + OFF_RED);

    const int tid  = threadIdx.x;
    const int lane = tid & 31;
    const int warp = tid >> 5;

    // ---- load tables into shared ----
    for (int i = tid; i < FDIM * NBINS; i += TPB) {
        const int f = i >> 5, bb = i & 31;
        sW[f * WPAD + bb] = W[i];
    }
    {
        const float4* IWv  = (const float4*)IW;
        float4*       sIWv = (float4*)sIW;
        const int niw = P * (NBINS * NBINS) / 4;
        for (int i = tid; i < niw; i += TPB) sIWv[i] = IWv[i];
    }

    const float c = intercept[0];
    int pi = 0, pj = 0;
    const bool havep = (lane < P);
    if (havep) { pi = pair_i[lane]; pj = pair_j[lane]; }
    const bool fast = (P == 32) &&
        __all_sync(0xffffffffu,
                   !havep || (pi == 2 * lane && pj == 2 * lane + 1));

    const float* sW_lane  = sW + lane * 8 * WPAD;
    // pair (4*lane) base: 4*lane pairs * 1024 floats/pair = lane*4096 floats
    // (R9 bug was lane*1024 here — wrong table for 24/32 pairs)
    const float* sIW_lane = sIW + (size_t)lane * 4096;

    const char*  xb      = (const char*)x;
    const size_t x_bytes = (size_t)B * ROW_BYTES;
    const int    nchunk  = (B + CHUNK_ROWS - 1) / CHUNK_ROWS;
    const uint32_t stage_u32 = (uint32_t)__cvta_generic_to_shared(stg);

    float s0 = 0.f, s0q = 0.f, s5 = 0.f, s5q = 0.f;

    __syncthreads();   // tables ready before stage/processing

    if (fast)
        run_pipeline<true >(xb, x_bytes, B, nchunk, stg, stage_u32,
                            sW_lane, sIW_lane, sIW, tid, lane, warp,
                            pi, pj, havep, c, out, s0, s0q, s5, s5q);
    else
        run_pipeline<false>(xb, x_bytes, B, nchunk, stg, stage_u32,
                            sW_lane, sIW_lane, sIW, tid, lane, warp,
                            pi, pj, havep, c, out, s0, s0q, s5, s5q);

    // ---- block-level fairness reduction (deterministic, no atomics) ----
    if (lane == 0) {
        sred[warp * 4 + 0] = (double)s0;  sred[warp * 4 + 1] = (double)s0q;
        sred[warp * 4 + 2] = (double)s5;  sred[warp * 4 + 3] = (double)s5q;
    }
    __syncthreads();
    __shared__ bool s_last;
    if (tid == 0) {
        double a0 = 0, a1 = 0, a2 = 0, a3 = 0;
        #pragma unroll 4
        for (int w = 0; w < WPB; w++) {
            a0 += sred[w * 4 + 0]; a1 += sred[w * 4 + 1];
            a2 += sred[w * 4 + 2]; a3 += sred[w * 4 + 3];
        }
        g_fair_part[blockIdx.x * 4 + 0] = a0;
        g_fair_part[blockIdx.x * 4 + 1] = a1;
        g_fair_part[blockIdx.x * 4 + 2] = a2;
        g_fair_part[blockIdx.x * 4 + 3] = a3;
        __threadfence();
        const unsigned int t = atomicAdd(&g_done, 1u);
        s_last = (t == (unsigned)(gridDim.x - 1));
    }
    __syncthreads();

    // ---- last block: final cross-block reduction (fixed order -> deterministic) ----
    if (s_last) {
        __threadfence();
        if (warp < 4) {
            double acc = 0.0;
            for (int b = lane; b < gridDim.x; b += 32)
                acc += g_fair_part[b * 4 + warp];
            #pragma unroll
            for (int o = 16; o > 0; o >>= 1)
                acc += __shfl_xor_sync(0xffffffffu, acc, o);
            if (lane == 0) sred[warp] = acc;
        }
        __syncthreads();
        if (tid == 0) {
            const double ss0 = sred[0], ss0q = sred[1];
            const double ss5 = sred[2], ss5q = sred[3];
            const double invB = 1.0 / (double)B;
            const double m0 = ss0 * invB, m5 = ss5 * invB;
            const double v0 = ss0q * invB - m0 * m0;   // population variance
            const double v5 = ss5q * invB - m5 * m5;
            out[B] = (float)(0.1 * (v0 + v5));
            g_done = 0;                                // reset for next replay
        }
    }
}

extern "C" void kernel_launch(void* const* d_in, const int* in_sizes, int n_in,
                              void* d_out, int out_size)
{
    const float* x         = (const float*)d_in[0];
    const float* W         = (const float*)d_in[1];
    const float* IW        = (const float*)d_in[2];
    const float* intercept = (const float*)d_in[3];
    // d_in[4] = bins (uniform linspace, reproduced analytically)
    const int*   pair_i    = (const int*)d_in[5];
    const int*   pair_j    = (const int*)d_in[6];

    const int B = in_sizes[0] / FDIM;
    const int P = in_sizes[2] / (NBINS * NBINS);
    float* out = (float*)d_out;

    cudaFuncSetAttribute(fair_ebm_main,
                         cudaFuncAttributeMaxDynamicSharedMemorySize, SMEM_TOTAL);

    fair_ebm_main<<<NBLK, TPB, SMEM_TOTAL>>>(x, W, IW, intercept, pair_i, pair_j,
                                             out, B, P);
}

// round 12
// speedup vs baseline: 1.2205x; 1.2205x over previous
#include <cuda_runtime.h>
#include <cuda_bf16.h>
#include <cstdint>

// Problem constants (fixed by the reference setup)
#define FDIM   256
#define NBINS  32
#define NBLK   148
#define TPB    512                // 16 warps -> 128 regs/thread budget
#define WPB    (TPB / 32)
#define WPAD   33                 // padded W row stride (bank decorrelation)
#define DEPTH  4                  // rows in flight per warp

// Per-block fairness partials: [block][ s0, s0sq, s5, s5sq ]
__device__ double       g_fair_part[NBLK * 4];
__device__ unsigned int g_done;   // zero at load; last block resets -> graph-replay safe

// x ~ uniform[0,1): (int)(v*32) == floor(v*32) == reference bin index (exact:
// every edge k/32 is exact fp32 and v*32 is an exact exponent shift).
// Do NOT fuse +base into an FFMA (rounding could cross an integer bin).

template<bool FAST>
__device__ __forceinline__ float row_val(
    float4 a, float4 b,
    const float* __restrict__ sW_lane,    // sW + lane*8*WPAD
    const float* __restrict__ sIW_lane,   // sIW + lane*4096 floats = pair 4*lane base
    const float* __restrict__ sIW,
    int lane, int pi, int pj, bool havep,
    float& s0, float& s0q, float& s5, float& s5q)
{
    float v[8] = {a.x, a.y, a.z, a.w, b.x, b.y, b.z, b.w};
    int id[8];
    #pragma unroll
    for (int j = 0; j < 8; j++) id[j] = (int)(v[j] * 32.0f);

    float g[8];
    #pragma unroll
    for (int j = 0; j < 8; j++) g[j] = sW_lane[j * WPAD + id[j]];

    float m = ((g[0] + g[1]) + (g[2] + g[3])) + ((g[4] + g[5]) + (g[6] + g[7]));

    // fairness: features 0,5 live on lane 0; accumulate unpredicated on all
    // lanes, only lane 0's accumulators are consumed.
    s0 += g[0];  s0q = fmaf(g[0], g[0], s0q);
    s5 += g[5];  s5q = fmaf(g[5], g[5], s5q);

    float inter = 0.0f;
    if (FAST) {
        if (lane < 8) {   // pairs 4l..4l+3 entirely local to lane l
            #pragma unroll
            for (int q = 0; q < 4; q++)
                inter += sIW_lane[q * 1024 + id[2 * q] * 32 + id[2 * q + 1]];
        }
    } else {
        unsigned int lo = ((unsigned)id[0]) | ((unsigned)id[1] << 8) |
                          ((unsigned)id[2] << 16) | ((unsigned)id[3] << 24);
        unsigned int hi = ((unsigned)id[4]) | ((unsigned)id[5] << 8) |
                          ((unsigned)id[6] << 16) | ((unsigned)id[7] << 24);
        unsigned int li  = __shfl_sync(0xffffffffu, lo, (pi >> 3) & 31);
        unsigned int hii = __shfl_sync(0xffffffffu, hi, (pi >> 3) & 31);
        unsigned int lj  = __shfl_sync(0xffffffffu, lo, (pj >> 3) & 31);
        unsigned int hjj = __shfl_sync(0xffffffffu, hi, (pj >> 3) & 31);
        if (havep) {
            const unsigned wi = ((pi & 4) ? hii : li) >> (8 * (pi & 3));
            const unsigned wj = ((pj & 4) ? hjj : lj) >> (8 * (pj & 3));
            inter = sIW[lane * (NBINS * NBINS) + (int)(wi & 0xff) * NBINS + (int)(wj & 0xff)];
        }
    }
    return m + inter;
}

template<bool FAST>
__device__ __forceinline__ void row_loop(
    const float* __restrict__ x, int B, int gw, int st,
    const float* __restrict__ sW_lane, const float* __restrict__ sIW_lane,
    const float* __restrict__ sIW,
    int lane, int pi, int pj, bool havep, float c, float* __restrict__ out,
    float& s0, float& s0q, float& s5, float& s5q)
{
    int row = gw;
    float4 A[DEPTH], Bv[DEPTH];
    bool   h[DEPTH];

    #pragma unroll
    for (int k = 0; k < DEPTH; k++) {
        h[k] = (row + k * st) < B;
        if (h[k]) {
            const float4* xp =
                (const float4*)(x + (size_t)(row + k * st) * FDIM) + (lane << 1);
            A[k] = xp[0];  Bv[k] = xp[1];
        }
    }

    while (h[0]) {
        const int rown = row + DEPTH * st;

        // prefetch next DEPTH rows (8 LDG.128 in flight while processing)
        float4 An[DEPTH], Bn[DEPTH];
        bool   hn[DEPTH];
        #pragma unroll
        for (int k = 0; k < DEPTH; k++) {
            hn[k] = (rown + k * st) < B;
            if (hn[k]) {
                const float4* xp =
                    (const float4*)(x + (size_t)(rown + k * st) * FDIM) + (lane << 1);
                An[k] = xp[0];  Bn[k] = xp[1];
            }
        }

        // compute DEPTH rows' pre-reduction values (warp-uniform guards)
        float t[DEPTH];
        #pragma unroll
        for (int k = 0; k < DEPTH; k++) {
            t[k] = 0.0f;
            if (h[k])
                t[k] = row_val<FAST>(A[k], Bv[k], sW_lane, sIW_lane, sIW,
                                     lane, pi, pj, havep, s0, s0q, s5, s5q);
        }

        // 4-way interleaved butterfly: exposed SHFL latency / DEPTH
        #pragma unroll
        for (int o = 16; o > 0; o >>= 1) {
            #pragma unroll
            for (int k = 0; k < DEPTH; k++)
                t[k] += __shfl_xor_sync(0xffffffffu, t[k], o);
        }

        if (lane == 0) {
            #pragma unroll
            for (int k = 0; k < DEPTH; k++)
                if (h[k]) out[row + k * st] = c + t[k];
        }

        #pragma unroll
        for (int k = 0; k < DEPTH; k++) { A[k] = An[k]; Bv[k] = Bn[k]; h[k] = hn[k]; }
        row = rown;
    }
}

__global__ __launch_bounds__(TPB, 1)
void fair_ebm_main(const float*  __restrict__ x,
                   const float*  __restrict__ W,          // [256, 32]
                   const float*  __restrict__ IW,         // [P, 32, 32]
                   const float*  __restrict__ intercept,  // [1]
                   const int*    __restrict__ pair_i,     // [P]
                   const int*    __restrict__ pair_j,     // [P]
                   float*        __restrict__ out,        // [B+1]
                   int B, int P)
{
    extern __shared__ char smem[];
    float*  sW   = (float*)smem;                                       // 33792 B
    float*  sIW  = (float*)(smem + FDIM * WPAD * 4);                   // P*4096 B
    double* sred = (double*)(smem + FDIM * WPAD * 4 + (size_t)P * 4096);

    const int tid  = threadIdx.x;
    const int lane = tid & 31;
    const int warp = tid >> 5;

    // ---- load tables into shared ----
    for (int i = tid; i < FDIM * NBINS; i += TPB) {
        const int f = i >> 5, bb = i & 31;
        sW[f * WPAD + bb] = W[i];
    }
    {
        const float4* IWv  = (const float4*)IW;
        float4*       sIWv = (float4*)sIW;
        const int niw = P * (NBINS * NBINS) / 4;
        for (int i = tid; i < niw; i += TPB) sIWv[i] = IWv[i];
    }
    __syncthreads();

    const float c = intercept[0];
    int pi = 0, pj = 0;
    const bool havep = (lane < P);
    if (havep) { pi = pair_i[lane]; pj = pair_j[lane]; }
    const bool fast = (P == 32) &&
        __all_sync(0xffffffffu,
                   !havep || (pi == 2 * lane && pj == 2 * lane + 1));

    const float* sW_lane  = sW + lane * 8 * WPAD;
    // pair (4*lane) base = 4*lane * 1024 floats; dereferenced only for lane<8
    const float* sIW_lane = sIW + (size_t)lane * 4096;

    float s0 = 0.f, s0q = 0.f, s5 = 0.f, s5q = 0.f;

    const int gw = blockIdx.x * WPB + warp;
    const int st = gridDim.x * WPB;

    if (fast)
        row_loop<true >(x, B, gw, st, sW_lane, sIW_lane, sIW,
                        lane, pi, pj, havep, c, out, s0, s0q, s5, s5q);
    else
        row_loop<false>(x, B, gw, st, sW_lane, sIW_lane, sIW,
                        lane, pi, pj, havep, c, out, s0, s0q, s5, s5q);

    // ---- block-level fairness reduction (deterministic, no atomics) ----
    if (lane == 0) {
        sred[warp * 4 + 0] = (double)s0;  sred[warp * 4 + 1] = (double)s0q;
        sred[warp * 4 + 2] = (double)s5;  sred[warp * 4 + 3] = (double)s5q;
    }
    __syncthreads();
    __shared__ bool s_last;
    if (tid == 0) {
        double a0 = 0, a1 = 0, a2 = 0, a3 = 0;
        #pragma unroll 4
        for (int w = 0; w < WPB; w++) {
            a0 += sred[w * 4 + 0]; a1 += sred[w * 4 + 1];
            a2 += sred[w * 4 + 2]; a3 += sred[w * 4 + 3];
        }
        g_fair_part[blockIdx.x * 4 + 0] = a0;
        g_fair_part[blockIdx.x * 4 + 1] = a1;
        g_fair_part[blockIdx.x * 4 + 2] = a2;
        g_fair_part[blockIdx.x * 4 + 3] = a3;
        __threadfence();
        const unsigned int t = atomicAdd(&g_done, 1u);
        s_last = (t == (unsigned)(gridDim.x - 1));
    }
    __syncthreads();

    // ---- last block: final cross-block reduction (fixed order -> deterministic) ----
    if (s_last) {
        __threadfence();
        if (warp < 4) {
            double acc = 0.0;
            for (int b = lane; b < gridDim.x; b += 32)
                acc += g_fair_part[b * 4 + warp];
            #pragma unroll
            for (int o = 16; o > 0; o >>= 1)
                acc += __shfl_xor_sync(0xffffffffu, acc, o);
            if (lane == 0) sred[warp] = acc;
        }
        __syncthreads();
        if (tid == 0) {
            const double ss0 = sred[0], ss0q = sred[1];
            const double ss5 = sred[2], ss5q = sred[3];
            const double invB = 1.0 / (double)B;
            const double m0 = ss0 * invB, m5 = ss5 * invB;
            const double v0 = ss0q * invB - m0 * m0;   // population variance
            const double v5 = ss5q * invB - m5 * m5;
            out[B] = (float)(0.1 * (v0 + v5));
            g_done = 0;                                // reset for next replay
        }
    }
}

extern "C" void kernel_launch(void* const* d_in, const int* in_sizes, int n_in,
                              void* d_out, int out_size)
{
    const float* x         = (const float*)d_in[0];
    const float* W         = (const float*)d_in[1];
    const float* IW        = (const float*)d_in[2];
    const float* intercept = (const float*)d_in[3];
    // d_in[4] = bins (uniform linspace, reproduced analytically)
    const int*   pair_i    = (const int*)d_in[5];
    const int*   pair_j    = (const int*)d_in[6];

    const int B = in_sizes[0] / FDIM;
    const int P = in_sizes[2] / (NBINS * NBINS);
    float* out = (float*)d_out;

    const size_t smem = (size_t)FDIM * WPAD * 4            // padded W
                      + (size_t)P * 4096                   // IW
                      + (size_t)WPB * 4 * sizeof(double);  // reduction scratch

    cudaFuncSetAttribute(fair_ebm_main,
                         cudaFuncAttributeMaxDynamicSharedMemorySize, (int)smem);

    fair_ebm_main<<<NBLK, TPB, smem>>>(x, W, IW, intercept, pair_i, pair_j,
                                       out, B, P);
}